// round 1
// baseline (speedup 1.0000x reference)
#include <cuda_runtime.h>

// DepthDeformConv: modulated deformable conv 3x3, stride 1, pad 1, dil 1.
// B=4, C=64, H=W=128, O=64, K=9. All fp32.
//
// Inputs (metadata order):
//   d_in[0] input  (4,64,128,128)
//   d_in[1] depth  (4,1,128,128)   -- unused by reference
//   d_in[2] offset (4,18,128,128)  -- (B, K, {y,x}, H, W)
//   d_in[3] mask   (4,9,128,128)
//   d_in[4] weight (64,64,3,3)
//   d_in[5] bias   (64,)
// out: (4,64,128,128) fp32
//
// Design: one block per (b, y, 32-pixel x-tile).
//   Phase A: 288 tap jobs -> 4 clipped indices + 4 fused weights (bilinear*mask*valid) in smem
//   Phase B: col[576][32] in smem (ck = c*9+k to match weight layout), coalesced gathers
//   Phase C: 64x576 @ 576x32 GEMM, 4o x 4pix register tiles, ck split 2-way,
//            packed fma.rn.f32x2 over pixel pairs (2 FMA/instr).

#define H_IMG 128
#define W_IMG 128
#define C_IN  64
#define O_OUT 64
#define KTAPS 9
#define CK    (C_IN * KTAPS)      // 576
#define TILE  32
#define NTHREADS 256
#define PLANE (H_IMG * W_IMG)     // 16384

// dynamic smem layout (bytes):
//   [0, 73728)        col      float[576][32]
//   [73728, 78336)    meta_i   int4[288]
//   [78336, 82944)    meta_w   float4[288]
//   scratch (phase C reduction) reuses [73728, 82944): ull[128][9] = 9216 B
#define SMEM_BYTES 82944
#define META_OFF   73728
#define METAW_OFF  78336

typedef unsigned long long ull;

__device__ __forceinline__ ull pack2(float lo, float hi) {
    ull d;
    asm("mov.b64 %0, {%1, %2};" : "=l"(d) : "f"(lo), "f"(hi));
    return d;
}
__device__ __forceinline__ float2 unpack2(ull v) {
    float2 r;
    asm("mov.b64 {%0, %1}, %2;" : "=f"(r.x), "=f"(r.y) : "l"(v));
    return r;
}
// Packed dual-FMA: d.lo = a.lo*b.lo + c.lo ; d.hi = a.hi*b.hi + c.hi
__device__ __forceinline__ ull fma2(ull a, ull b, ull c) {
    ull d;
    asm("fma.rn.f32x2 %0, %1, %2, %3;" : "=l"(d) : "l"(a), "l"(b), "l"(c));
    return d;
}

extern __shared__ char smem_raw[];

__global__ __launch_bounds__(NTHREADS, 2)
void ddc_kernel(const float* __restrict__ input,
                const float* __restrict__ offset,
                const float* __restrict__ mask,
                const float* __restrict__ weight,
                const float* __restrict__ bias,
                float* __restrict__ out)
{
    float*  col    = (float*)smem_raw;
    int4*   meta_i = (int4*)(smem_raw + META_OFF);
    float4* meta_w = (float4*)(smem_raw + METAW_OFF);

    const int bid = blockIdx.x;
    const int xt  = (bid & 3) * TILE;      // x tile start
    const int y   = (bid >> 2) & 127;
    const int b   = bid >> 9;
    const int tid = threadIdx.x;

    // ---------------- Phase A: sampling metadata (288 tap jobs) ----------------
    for (int i = tid; i < KTAPS * TILE; i += NTHREADS) {
        int pix = i & 31;
        int k   = i >> 5;                  // 0..8
        int ky  = k / 3;
        int kx  = k - ky * 3;
        int x   = xt + pix;

        int obase = ((b * 18 + 2 * k) * H_IMG + y) * W_IMG + x;
        float oy = offset[obase];
        float ox = offset[obase + PLANE];
        float m  = mask[((b * 9 + k) * H_IMG + y) * W_IMG + x];

        float py = (float)(y - 1 + ky) + oy;
        float px = (float)(x - 1 + kx) + ox;

        float y0f = floorf(py), x0f = floorf(px);
        int y0 = (int)y0f, x0 = (int)x0f;
        float wy = py - y0f, wx = px - x0f;
        int y1 = y0 + 1, x1 = x0 + 1;

        float vy0 = (y0 >= 0 && y0 < H_IMG) ? 1.f : 0.f;
        float vy1 = (y1 >= 0 && y1 < H_IMG) ? 1.f : 0.f;
        float vx0 = (x0 >= 0 && x0 < W_IMG) ? 1.f : 0.f;
        float vx1 = (x1 >= 0 && x1 < W_IMG) ? 1.f : 0.f;

        int yc0 = min(max(y0, 0), H_IMG - 1);
        int yc1 = min(max(y1, 0), H_IMG - 1);
        int xc0 = min(max(x0, 0), W_IMG - 1);
        int xc1 = min(max(x1, 0), W_IMG - 1);

        float4 w;
        w.x = (1.f - wy) * (1.f - wx) * m * vy0 * vx0;
        w.y = (1.f - wy) * wx         * m * vy0 * vx1;
        w.z = wy         * (1.f - wx) * m * vy1 * vx0;
        w.w = wy         * wx         * m * vy1 * vx1;

        meta_i[i] = make_int4(yc0 * W_IMG + xc0, yc0 * W_IMG + xc1,
                              yc1 * W_IMG + xc0, yc1 * W_IMG + xc1);
        meta_w[i] = w;
    }
    __syncthreads();

    // ---------------- Phase B: build col[576][32] ----------------
    const float* inb = input + (size_t)b * C_IN * PLANE;
    for (int e = tid; e < CK * TILE; e += NTHREADS) {
        int pix = e & 31;
        int ck  = e >> 5;
        int c   = ck / 9;
        int k   = ck - c * 9;
        int tap = k * TILE + pix;
        int4   ii = meta_i[tap];
        float4 ww = meta_w[tap];
        const float* plane = inb + c * PLANE;
        float v = ww.x * __ldg(plane + ii.x)
                + ww.y * __ldg(plane + ii.y)
                + ww.z * __ldg(plane + ii.z)
                + ww.w * __ldg(plane + ii.w);
        col[ck * TILE + pix] = v;
    }
    __syncthreads();

    // ---------------- Phase C: GEMM 64x576 @ 576x32 ----------------
    // 256 threads = 2 ck-halves x 128 slots; slot = (o quad, pixel quad)
    const int slot = tid & 127;
    const int half = tid >> 7;
    const int op   = slot >> 3;        // 0..15 -> o0 = op*4
    const int pixg = slot & 7;         // 0..7  -> pix0 = pixg*4
    const int o0   = op * 4;

    const ulonglong2* colv = (const ulonglong2*)col;  // 8 ulonglong2 per ck row

    ull acc[4][2];
    #pragma unroll
    for (int j = 0; j < 4; j++) { acc[j][0] = 0ULL; acc[j][1] = 0ULL; }

    const float* wrow0 = weight + (size_t)(o0 + 0) * CK;
    const float* wrow1 = weight + (size_t)(o0 + 1) * CK;
    const float* wrow2 = weight + (size_t)(o0 + 2) * CK;
    const float* wrow3 = weight + (size_t)(o0 + 3) * CK;

    const int ck0 = half * (CK / 2);   // 0 or 288
    #pragma unroll 2
    for (int ck = ck0; ck < ck0 + CK / 2; ck += 4) {
        float4 w40 = *(const float4*)(wrow0 + ck);
        float4 w41 = *(const float4*)(wrow1 + ck);
        float4 w42 = *(const float4*)(wrow2 + ck);
        float4 w43 = *(const float4*)(wrow3 + ck);
        const float* wf[4] = { (const float*)&w40, (const float*)&w41,
                               (const float*)&w42, (const float*)&w43 };
        #pragma unroll
        for (int u = 0; u < 4; u++) {
            ulonglong2 cv = colv[(ck + u) * 8 + pixg];   // pixels (0,1) and (2,3)
            #pragma unroll
            for (int j = 0; j < 4; j++) {
                float wv = wf[j][u];
                ull wp = pack2(wv, wv);
                acc[j][0] = fma2(wp, cv.x, acc[j][0]);
                acc[j][1] = fma2(wp, cv.y, acc[j][1]);
            }
        }
    }

    // ---------------- reduction across the 2 ck-halves ----------------
    ull* scratch = (ull*)(smem_raw + META_OFF);   // 128 slots * 9 ull (padded) = 9216 B
    if (half == 1) {
        #pragma unroll
        for (int j = 0; j < 4; j++) {
            scratch[slot * 9 + j * 2 + 0] = acc[j][0];
            scratch[slot * 9 + j * 2 + 1] = acc[j][1];
        }
    }
    __syncthreads();
    if (half == 0) {
        #pragma unroll
        for (int j = 0; j < 4; j++) {
            float2 a0 = unpack2(acc[j][0]);
            float2 a1 = unpack2(acc[j][1]);
            float2 s0 = unpack2(scratch[slot * 9 + j * 2 + 0]);
            float2 s1 = unpack2(scratch[slot * 9 + j * 2 + 1]);
            float bv = bias[o0 + j];
            float4 r;
            r.x = a0.x + s0.x + bv;
            r.y = a0.y + s0.y + bv;
            r.z = a1.x + s1.x + bv;
            r.w = a1.y + s1.y + bv;
            int oidx = ((b * O_OUT + o0 + j) * H_IMG + y) * W_IMG + xt + pixg * 4;
            *(float4*)&out[oidx] = r;
        }
    }
}

extern "C" void kernel_launch(void* const* d_in, const int* in_sizes, int n_in,
                              void* d_out, int out_size)
{
    const float* input  = (const float*)d_in[0];
    // d_in[1] = depth, unused by the reference computation
    const float* offset = (const float*)d_in[2];
    const float* mask   = (const float*)d_in[3];
    const float* weight = (const float*)d_in[4];
    const float* bias   = (const float*)d_in[5];
    float* out = (float*)d_out;

    cudaFuncSetAttribute(ddc_kernel,
                         cudaFuncAttributeMaxDynamicSharedMemorySize, SMEM_BYTES);

    // grid: b (4) * y (128) * x-tiles (4) = 2048 blocks
    ddc_kernel<<<2048, NTHREADS, SMEM_BYTES>>>(input, offset, mask, weight, bias, out);
}